// round 5
// baseline (speedup 1.0000x reference)
#include <cuda_runtime.h>
#include <cuda_bf16.h>

// ColorQuantizer: out = PALETTE[argmin_p ||MLP(x) - pal_p||]
// (stop_gradient(hard - soft) + soft == hard numerically; softmax/sqrt are
//  monotone so argmax(weights) == argmin(distance) == argmax(dot - 0.5*|pal|^2))
//
// Inputs (metadata order): x[32,3,512,512] f32, W1[3,32], b1[32], W2[32,3], b2[3]
// Output: [32,3,512,512] f32

typedef unsigned long long u64;

#define B_DIM  32
#define HW     262144          // 512*512
#define TPB    256
#define ITER   8               // vec4 items per thread
#define GRIDX  (HW / 4 / (TPB * ITER))   // 65536 / 2048 = 32

__device__ __forceinline__ u64 pk2(float lo, float hi) {
    u64 d; asm("mov.b64 %0, {%1, %2};" : "=l"(d) : "f"(lo), "f"(hi)); return d;
}
__device__ __forceinline__ void up2(float& lo, float& hi, u64 d) {
    asm("mov.b64 {%0, %1}, %2;" : "=f"(lo), "=f"(hi) : "l"(d));
}
__device__ __forceinline__ u64 ffma2(u64 a, u64 b, u64 c) {
    u64 d; asm("fma.rn.f32x2 %0, %1, %2, %3;" : "=l"(d) : "l"(a), "l"(b), "l"(c));
    return d;
}

__global__ __launch_bounds__(TPB) void color_quant_kernel(
    const float* __restrict__ x,
    const float* __restrict__ W1,   // [3][32] row-major
    const float* __restrict__ b1,   // [32]
    const float* __restrict__ W2,   // [32][3] row-major
    const float* __restrict__ b2,   // [3]
    float* __restrict__ out)
{
    // Shared: weights pre-duplicated into both halves of f32x2 lanes.
    // sW1[j]  = {w0,w0, w1,w1, w2,w2, b1,b1}        (8 floats, 2x LDS.128)
    // sW2[j]  = {u0,u0, u1,u1, u2,u2, 0,0}
    // sPal[p] = {px,px, py,py, pz,pz, c,c},  c = -0.5*|pal_p|^2
    __shared__ __align__(16) float sW1[32 * 8];
    __shared__ __align__(16) float sW2[32 * 8];
    __shared__ __align__(16) float sPal[16 * 8];
    __shared__ float sGat[48];      // palette gather table [16][3]

    const int tid = threadIdx.x;

    if (tid < 32) {
        const int j = tid;
        float w0 = W1[j], w1 = W1[32 + j], w2 = W1[64 + j], bb = b1[j];
        float4* v = (float4*)(sW1 + j * 8);
        v[0] = make_float4(w0, w0, w1, w1);
        v[1] = make_float4(w2, w2, bb, bb);
        float u0 = W2[3 * j], u1 = W2[3 * j + 1], u2 = W2[3 * j + 2];
        float4* q = (float4*)(sW2 + j * 8);
        q[0] = make_float4(u0, u0, u1, u1);
        q[1] = make_float4(u2, u2, 0.f, 0.f);
    }
    if (tid < 16) {
        // raw palette colors (0..255); convert exactly like numpy fp32:
        // pal = (c / 255.0f) * 2.0f - 1.0f, each op round-to-nearest.
        const float C[16][3] = {
            {0,0,0},{255,255,255},{255,0,0},{0,255,0},{0,0,255},{255,255,0},
            {255,0,255},{0,255,255},{128,128,128},{128,0,0},{0,128,0},{0,0,128},
            {128,128,0},{128,0,128},{0,128,128},{192,192,192}};
        float px = __fsub_rn(__fmul_rn(__fdiv_rn(C[tid][0], 255.0f), 2.0f), 1.0f);
        float py = __fsub_rn(__fmul_rn(__fdiv_rn(C[tid][1], 255.0f), 2.0f), 1.0f);
        float pz = __fsub_rn(__fmul_rn(__fdiv_rn(C[tid][2], 255.0f), 2.0f), 1.0f);
        float n  = __fmaf_rn(pz, pz, __fmaf_rn(py, py, __fmul_rn(px, px)));
        float cc = -0.5f * n;
        float4* t = (float4*)(sPal + tid * 8);
        t[0] = make_float4(px, px, py, py);
        t[1] = make_float4(pz, pz, cc, cc);
        sGat[tid * 3 + 0] = px;
        sGat[tid * 3 + 1] = py;
        sGat[tid * 3 + 2] = pz;
    }
    __syncthreads();

    const float bz0 = b2[0], bz1 = b2[1], bz2 = b2[2];
    const u64 Bp0 = pk2(bz0, bz0), Bp1 = pk2(bz1, bz1), Bp2 = pk2(bz2, bz2);

    const float* xb = x   + (size_t)blockIdx.y * (3 * HW);
    float*       ob = out + (size_t)blockIdx.y * (3 * HW);
    const int it0 = blockIdx.x * (TPB * ITER) + tid;

    const ulonglong2* w1v = (const ulonglong2*)sW1;
    const ulonglong2* w2v = (const ulonglong2*)sW2;
    const ulonglong2* pv  = (const ulonglong2*)sPal;

    #pragma unroll 1
    for (int k = 0; k < ITER; k++) {
        const int r = (it0 + k * TPB) * 4;

        // 4 pixels: one float4 per channel (coalesced LDG.128)
        float4 c0 = *(const float4*)(xb + r);
        float4 c1 = *(const float4*)(xb + HW + r);
        float4 c2 = *(const float4*)(xb + 2 * HW + r);
        u64 X0a = pk2(c0.x, c0.y), X0b = pk2(c0.z, c0.w);
        u64 X1a = pk2(c1.x, c1.y), X1b = pk2(c1.z, c1.w);
        u64 X2a = pk2(c2.x, c2.y), X2b = pk2(c2.z, c2.w);

        // processed accumulators (init = b2), pairs (p0,p1) and (p2,p3)
        u64 A0 = Bp0, A0b = Bp0;
        u64 A1 = Bp1, A1b = Bp1;
        u64 A2 = Bp2, A2b = Bp2;

        // fused layer1 (relu) + layer2: hidden_j computed and consumed
        #pragma unroll
        for (int j = 0; j < 32; j++) {
            ulonglong2 Wa = w1v[2 * j];       // {w0w0, w1w1}
            ulonglong2 Wb = w1v[2 * j + 1];   // {w2w2, bb}
            u64 h = ffma2(X0a, Wa.x, Wb.y);
            h = ffma2(X1a, Wa.y, h);
            h = ffma2(X2a, Wb.x, h);
            u64 g = ffma2(X0b, Wa.x, Wb.y);
            g = ffma2(X1b, Wa.y, g);
            g = ffma2(X2b, Wb.x, g);
            float lo, hi;
            up2(lo, hi, h); lo = fmaxf(lo, 0.f); hi = fmaxf(hi, 0.f); h = pk2(lo, hi);
            up2(lo, hi, g); lo = fmaxf(lo, 0.f); hi = fmaxf(hi, 0.f); g = pk2(lo, hi);
            ulonglong2 Ua = w2v[2 * j];       // {u0u0, u1u1}
            ulonglong2 Ub = w2v[2 * j + 1];   // {u2u2, 0}
            A0  = ffma2(h, Ua.x, A0);  A0b = ffma2(g, Ua.x, A0b);
            A1  = ffma2(h, Ua.y, A1);  A1b = ffma2(g, Ua.y, A1b);
            A2  = ffma2(h, Ub.x, A2);  A2b = ffma2(g, Ub.x, A2b);
        }

        // argmax_p of (proc . pal_p - 0.5*|pal_p|^2); strict > keeps first index
        float bs0, bs1, bs2, bs3;
        int i0 = 0, i1 = 0, i2 = 0, i3 = 0;
        {
            ulonglong2 Pa = pv[0], Pb = pv[1];
            u64 t = ffma2(A0, Pa.x, Pb.y); t = ffma2(A1, Pa.y, t); t = ffma2(A2, Pb.x, t);
            up2(bs0, bs1, t);
            u64 s = ffma2(A0b, Pa.x, Pb.y); s = ffma2(A1b, Pa.y, s); s = ffma2(A2b, Pb.x, s);
            up2(bs2, bs3, s);
        }
        #pragma unroll
        for (int p = 1; p < 16; p++) {
            ulonglong2 Pa = pv[2 * p], Pb = pv[2 * p + 1];
            u64 t = ffma2(A0, Pa.x, Pb.y); t = ffma2(A1, Pa.y, t); t = ffma2(A2, Pb.x, t);
            float t0, t1; up2(t0, t1, t);
            u64 s = ffma2(A0b, Pa.x, Pb.y); s = ffma2(A1b, Pa.y, s); s = ffma2(A2b, Pb.x, s);
            float t2, t3; up2(t2, t3, s);
            if (t0 > bs0) { bs0 = t0; i0 = p; }
            if (t1 > bs1) { bs1 = t1; i1 = p; }
            if (t2 > bs2) { bs2 = t2; i2 = p; }
            if (t3 > bs3) { bs3 = t3; i3 = p; }
        }

        // gather hard-quantized colors, store coalesced STG.128 per channel
        float4 o0 = make_float4(sGat[i0 * 3 + 0], sGat[i1 * 3 + 0],
                                sGat[i2 * 3 + 0], sGat[i3 * 3 + 0]);
        float4 o1 = make_float4(sGat[i0 * 3 + 1], sGat[i1 * 3 + 1],
                                sGat[i2 * 3 + 1], sGat[i3 * 3 + 1]);
        float4 o2 = make_float4(sGat[i0 * 3 + 2], sGat[i1 * 3 + 2],
                                sGat[i2 * 3 + 2], sGat[i3 * 3 + 2]);
        *(float4*)(ob + r)          = o0;
        *(float4*)(ob + HW + r)     = o1;
        *(float4*)(ob + 2 * HW + r) = o2;
    }
}

extern "C" void kernel_launch(void* const* d_in, const int* in_sizes, int n_in,
                              void* d_out, int out_size) {
    const float* x  = (const float*)d_in[0];
    const float* W1 = (const float*)d_in[1];
    const float* b1 = (const float*)d_in[2];
    const float* W2 = (const float*)d_in[3];
    const float* b2 = (const float*)d_in[4];
    float* out = (float*)d_out;

    dim3 grid(GRIDX, B_DIM);   // 32 x 32 = 1024 CTAs, 8 vec4 items/thread
    dim3 block(TPB);
    color_quant_kernel<<<grid, block>>>(x, W1, b1, W2, b2, out);
}

// round 6
// speedup vs baseline: 3.6785x; 3.6785x over previous
#include <cuda_runtime.h>
#include <cuda_bf16.h>

// ColorQuantizer: out = PALETTE[argmin_p ||MLP(x) - pal_p||]
// (stop_gradient(hard - soft) + soft == hard numerically; softmax/sqrt are
//  monotone so argmax(weights) == argmin(distance) == argmax(dot - 0.5*|pal|^2))
//
// Inputs (metadata order): x[32,3,512,512] f32, W1[3,32], b1[32], W2[32,3], b2[3]
// Output: [32,3,512,512] f32

typedef unsigned long long u64;

#define B_DIM  32
#define HW     262144          // 512*512
#define TPB    256
#define ITER   4               // vec4 items per thread
#define GRIDX  (HW / 4 / (TPB * ITER))   // 65536 / 1024 = 64

__device__ __forceinline__ u64 pk2(float lo, float hi) {
    u64 d; asm("mov.b64 %0, {%1, %2};" : "=l"(d) : "f"(lo), "f"(hi)); return d;
}
__device__ __forceinline__ void up2(float& lo, float& hi, u64 d) {
    asm("mov.b64 {%0, %1}, %2;" : "=f"(lo), "=f"(hi) : "l"(d));
}
__device__ __forceinline__ u64 ffma2(u64 a, u64 b, u64 c) {
    u64 d; asm("fma.rn.f32x2 %0, %1, %2, %3;" : "=l"(d) : "l"(a), "l"(b), "l"(c));
    return d;
}

__global__ __launch_bounds__(TPB, 2) void color_quant_kernel(
    const float* __restrict__ x,
    const float* __restrict__ W1,   // [3][32] row-major
    const float* __restrict__ b1,   // [32]
    const float* __restrict__ W2,   // [32][3] row-major
    const float* __restrict__ b2,   // [3]
    float* __restrict__ out)
{
    // Shared: weights pre-duplicated into both halves of f32x2 lanes.
    // sW1[j]  = {w0,w0, w1,w1, w2,w2, b1,b1}        (2x LDS.128)
    // sW2[j]  = {u0,u0, u1,u1, u2,u2, 0,0}
    // sPal[p] = {px,px, py,py, pz,pz, c,c},  c = -0.5*|pal_p|^2
    __shared__ __align__(16) float sW1[32 * 8];
    __shared__ __align__(16) float sW2[32 * 8];
    __shared__ __align__(16) float sPal[16 * 8];
    __shared__ float sGat[48];      // palette gather table [16][3]

    const int tid = threadIdx.x;

    if (tid < 32) {
        const int j = tid;
        float w0 = W1[j], w1 = W1[32 + j], w2 = W1[64 + j], bb = b1[j];
        float4* v = (float4*)(sW1 + j * 8);
        v[0] = make_float4(w0, w0, w1, w1);
        v[1] = make_float4(w2, w2, bb, bb);
        float u0 = W2[3 * j], u1 = W2[3 * j + 1], u2 = W2[3 * j + 2];
        float4* q = (float4*)(sW2 + j * 8);
        q[0] = make_float4(u0, u0, u1, u1);
        q[1] = make_float4(u2, u2, 0.f, 0.f);
    }
    if (tid < 16) {
        // pal = (c/255)*2 - 1, each op round-to-nearest fp32 (matches numpy)
        const float C[16][3] = {
            {0,0,0},{255,255,255},{255,0,0},{0,255,0},{0,0,255},{255,255,0},
            {255,0,255},{0,255,255},{128,128,128},{128,0,0},{0,128,0},{0,0,128},
            {128,128,0},{128,0,128},{0,128,128},{192,192,192}};
        float px = __fsub_rn(__fmul_rn(__fdiv_rn(C[tid][0], 255.0f), 2.0f), 1.0f);
        float py = __fsub_rn(__fmul_rn(__fdiv_rn(C[tid][1], 255.0f), 2.0f), 1.0f);
        float pz = __fsub_rn(__fmul_rn(__fdiv_rn(C[tid][2], 255.0f), 2.0f), 1.0f);
        float n  = __fmaf_rn(pz, pz, __fmaf_rn(py, py, __fmul_rn(px, px)));
        float cc = -0.5f * n;
        float4* t = (float4*)(sPal + tid * 8);
        t[0] = make_float4(px, px, py, py);
        t[1] = make_float4(pz, pz, cc, cc);
        sGat[tid * 3 + 0] = px;
        sGat[tid * 3 + 1] = py;
        sGat[tid * 3 + 2] = pz;
    }
    __syncthreads();

    const float bz0 = b2[0], bz1 = b2[1], bz2 = b2[2];
    const u64 Bp0 = pk2(bz0, bz0), Bp1 = pk2(bz1, bz1), Bp2 = pk2(bz2, bz2);

    const float* xb = x   + (size_t)blockIdx.y * (3 * HW);
    float*       ob = out + (size_t)blockIdx.y * (3 * HW);
    const int it0 = blockIdx.x * (TPB * ITER) + tid;

    const ulonglong2* w1v = (const ulonglong2*)sW1;
    const ulonglong2* w2v = (const ulonglong2*)sW2;
    const ulonglong2* pv  = (const ulonglong2*)sPal;

    // software-pipelined global loads: fetch k+1 while computing k
    float4 c0 = *(const float4*)(xb + it0 * 4);
    float4 c1 = *(const float4*)(xb + HW + it0 * 4);
    float4 c2 = *(const float4*)(xb + 2 * HW + it0 * 4);

    #pragma unroll 1
    for (int k = 0; k < ITER; k++) {
        const int r = (it0 + k * TPB) * 4;

        float4 n0, n1, n2;
        if (k + 1 < ITER) {
            const int rn = (it0 + (k + 1) * TPB) * 4;
            n0 = *(const float4*)(xb + rn);
            n1 = *(const float4*)(xb + HW + rn);
            n2 = *(const float4*)(xb + 2 * HW + rn);
        }

        u64 X0a = pk2(c0.x, c0.y), X0b = pk2(c0.z, c0.w);
        u64 X1a = pk2(c1.x, c1.y), X1b = pk2(c1.z, c1.w);
        u64 X2a = pk2(c2.x, c2.y), X2b = pk2(c2.z, c2.w);

        // processed accumulators (init = b2), pairs (p0,p1) and (p2,p3)
        u64 A0 = Bp0, A0b = Bp0;
        u64 A1 = Bp1, A1b = Bp1;
        u64 A2 = Bp2, A2b = Bp2;

        // fused layer1 (relu) + layer2; unroll 4 => LDS pipelined, no reg blowup
        #pragma unroll 4
        for (int j = 0; j < 32; j++) {
            ulonglong2 Wa = w1v[2 * j];       // {w0w0, w1w1}
            ulonglong2 Wb = w1v[2 * j + 1];   // {w2w2, bb}
            u64 h = ffma2(X0a, Wa.x, Wb.y);
            u64 g = ffma2(X0b, Wa.x, Wb.y);
            h = ffma2(X1a, Wa.y, h);
            g = ffma2(X1b, Wa.y, g);
            h = ffma2(X2a, Wb.x, h);
            g = ffma2(X2b, Wb.x, g);
            float lo, hi;
            up2(lo, hi, h); lo = fmaxf(lo, 0.f); hi = fmaxf(hi, 0.f); h = pk2(lo, hi);
            up2(lo, hi, g); lo = fmaxf(lo, 0.f); hi = fmaxf(hi, 0.f); g = pk2(lo, hi);
            ulonglong2 Ua = w2v[2 * j];       // {u0u0, u1u1}
            ulonglong2 Ub = w2v[2 * j + 1];   // {u2u2, 0}
            A0  = ffma2(h, Ua.x, A0);  A0b = ffma2(g, Ua.x, A0b);
            A1  = ffma2(h, Ua.y, A1);  A1b = ffma2(g, Ua.y, A1b);
            A2  = ffma2(h, Ub.x, A2);  A2b = ffma2(g, Ub.x, A2b);
        }

        // argmax_p of (proc . pal_p - 0.5*|pal_p|^2); strict > keeps first index
        float bs0, bs1, bs2, bs3;
        int i0 = 0, i1 = 0, i2 = 0, i3 = 0;
        {
            ulonglong2 Pa = pv[0], Pb = pv[1];
            u64 t = ffma2(A0, Pa.x, Pb.y); t = ffma2(A1, Pa.y, t); t = ffma2(A2, Pb.x, t);
            up2(bs0, bs1, t);
            u64 s = ffma2(A0b, Pa.x, Pb.y); s = ffma2(A1b, Pa.y, s); s = ffma2(A2b, Pb.x, s);
            up2(bs2, bs3, s);
        }
        #pragma unroll 5
        for (int p = 1; p < 16; p++) {
            ulonglong2 Pa = pv[2 * p], Pb = pv[2 * p + 1];
            u64 t = ffma2(A0, Pa.x, Pb.y); t = ffma2(A1, Pa.y, t); t = ffma2(A2, Pb.x, t);
            u64 s = ffma2(A0b, Pa.x, Pb.y); s = ffma2(A1b, Pa.y, s); s = ffma2(A2b, Pb.x, s);
            float t0, t1; up2(t0, t1, t);
            float t2, t3; up2(t2, t3, s);
            if (t0 > bs0) { bs0 = t0; i0 = p; }
            if (t1 > bs1) { bs1 = t1; i1 = p; }
            if (t2 > bs2) { bs2 = t2; i2 = p; }
            if (t3 > bs3) { bs3 = t3; i3 = p; }
        }

        // gather hard-quantized colors, store coalesced STG.128 per channel
        float4 o0 = make_float4(sGat[i0 * 3 + 0], sGat[i1 * 3 + 0],
                                sGat[i2 * 3 + 0], sGat[i3 * 3 + 0]);
        float4 o1 = make_float4(sGat[i0 * 3 + 1], sGat[i1 * 3 + 1],
                                sGat[i2 * 3 + 1], sGat[i3 * 3 + 1]);
        float4 o2 = make_float4(sGat[i0 * 3 + 2], sGat[i1 * 3 + 2],
                                sGat[i2 * 3 + 2], sGat[i3 * 3 + 2]);
        *(float4*)(ob + r)          = o0;
        *(float4*)(ob + HW + r)     = o1;
        *(float4*)(ob + 2 * HW + r) = o2;

        c0 = n0; c1 = n1; c2 = n2;
    }
}

extern "C" void kernel_launch(void* const* d_in, const int* in_sizes, int n_in,
                              void* d_out, int out_size) {
    const float* x  = (const float*)d_in[0];
    const float* W1 = (const float*)d_in[1];
    const float* b1 = (const float*)d_in[2];
    const float* W2 = (const float*)d_in[3];
    const float* b2 = (const float*)d_in[4];
    float* out = (float*)d_out;

    dim3 grid(GRIDX, B_DIM);   // 64 x 32 = 2048 CTAs, 4 vec4 items/thread
    dim3 block(TPB);
    color_quant_kernel<<<grid, block>>>(x, W1, b1, W2, b2, out);
}